// round 3
// baseline (speedup 1.0000x reference)
#include <cuda_runtime.h>

// ---------------------------------------------------------------------------
// GroundingNet fused forward, fp32 baseline (FFMA-bound by design this round).
//   node: relu(bn1(X@W1+b1)) -> relu(bn2(@W2+b2)) -> relu(@W3+b3) -> sigmoid(@Wi+bi)
//   edge: gather(attr[src],attr[dst]) -> relu(@ew1+eb1) -> relu(@ew2+eb2) -> sigmoid(@eiw+eib)
// ---------------------------------------------------------------------------

namespace {
constexpr int Bn  = 32;
constexpr int Nn  = 512;
constexpr int Fn  = 1024;
constexpr int H1n = 512;
constexpr int H2n = 256;
constexpr int H3n = 128;
constexpr int NCn = 8;
constexpr int En  = 32768;                 // edges per batch
constexpr int ROWS = Bn * Nn;              // 16384
constexpr int TEn  = Bn * En;              // 1048576 total edges
constexpr float BN_EPS = 1e-5f;
constexpr float INV_POS = 1.0f / 1024.0f;
}

// scratch (static device allocation — no runtime allocs)
__device__ float g_h1[ROWS * H1n];
__device__ float g_h2[ROWS * H2n];
__device__ float g_h3[ROWS * H3n];

static __device__ __forceinline__ float sigmoidf_(float x) {
    return 1.0f / (1.0f + __expf(-x));
}

// ---------------------------------------------------------------------------
// Tiled SGEMM with fused epilogue.
//   C[M,N] = epi(A[M,K] @ W[K,N])
//   EPI 0: BN + ReLU  (y = s*acc + t, s = g*rsqrt(rv+eps), t = bnb + s*(bias-rm))
//   EPI 1: bias + ReLU
// BM=BN=128, BK=8, 256 threads, 8x8 per-thread tile, double-buffered smem.
// Requires M%128==0, N%128==0, K%8==0 (holds for all three layers).
// ---------------------------------------------------------------------------
template<int EPI>
__global__ __launch_bounds__(256, 2)
void sgemm_fused(const float* __restrict__ A, const float* __restrict__ W,
                 const float* __restrict__ bias,
                 const float* __restrict__ bng, const float* __restrict__ bnb,
                 const float* __restrict__ bnrm, const float* __restrict__ bnrv,
                 float* __restrict__ C, int M, int N, int K)
{
    constexpr int BM = 128, BN = 128, BK = 8, TM = 8, TN = 8;
    __shared__ float As[2][BK][BM];
    __shared__ float Bs[2][BK][BN];

    const int m0  = blockIdx.y * BM;
    const int n0  = blockIdx.x * BN;
    const int tid = threadIdx.x;
    const int tx  = tid & 15;   // N direction (16 * TN = 128)
    const int ty  = tid >> 4;   // M direction (16 * TM = 128)

    // global->smem load mapping (one float4 per thread per tile)
    const int arow = tid >> 1;            // 0..127
    const int acol = (tid & 1) * 4;       // 0 or 4
    const int wrow = tid >> 5;            // 0..7
    const int wcol = (tid & 31) * 4;      // 0..124

    const float* Aptr = A + (long)(m0 + arow) * K + acol;
    const float* Wptr = W + (long)wrow * N + n0 + wcol;

    float acc[TM][TN];
#pragma unroll
    for (int i = 0; i < TM; i++)
#pragma unroll
        for (int j = 0; j < TN; j++) acc[i][j] = 0.0f;

    // preload stage 0
    {
        float4 av = *(const float4*)Aptr;
        As[0][acol + 0][arow] = av.x;
        As[0][acol + 1][arow] = av.y;
        As[0][acol + 2][arow] = av.z;
        As[0][acol + 3][arow] = av.w;
        *(float4*)&Bs[0][wrow][wcol] = *(const float4*)Wptr;
    }
    __syncthreads();

    const int T = K / BK;
    for (int t = 0; t < T; t++) {
        float4 av, wv;
        if (t + 1 < T) {
            av = *(const float4*)(Aptr + (t + 1) * BK);
            wv = *(const float4*)(Wptr + (long)(t + 1) * BK * N);
        }
        const int cur = t & 1;
#pragma unroll
        for (int kk = 0; kk < BK; kk++) {
            float a[TM], b[TN];
            *(float4*)&a[0] = *(const float4*)&As[cur][kk][ty * TM];
            *(float4*)&a[4] = *(const float4*)&As[cur][kk][ty * TM + 4];
            *(float4*)&b[0] = *(const float4*)&Bs[cur][kk][tx * TN];
            *(float4*)&b[4] = *(const float4*)&Bs[cur][kk][tx * TN + 4];
#pragma unroll
            for (int i = 0; i < TM; i++)
#pragma unroll
                for (int j = 0; j < TN; j++)
                    acc[i][j] = fmaf(a[i], b[j], acc[i][j]);
        }
        if (t + 1 < T) {
            const int nxt = cur ^ 1;
            As[nxt][acol + 0][arow] = av.x;
            As[nxt][acol + 1][arow] = av.y;
            As[nxt][acol + 2][arow] = av.z;
            As[nxt][acol + 3][arow] = av.w;
            *(float4*)&Bs[nxt][wrow][wcol] = wv;
            __syncthreads();
        }
    }

    // fused epilogue
    float s[TN], tt[TN];
#pragma unroll
    for (int j = 0; j < TN; j++) {
        const int col = n0 + tx * TN + j;
        if (EPI == 0) {
            const float sc = bng[col] * rsqrtf(bnrv[col] + BN_EPS);
            s[j]  = sc;
            tt[j] = bnb[col] + sc * (bias[col] - bnrm[col]);
        } else {
            s[j]  = 1.0f;
            tt[j] = bias[col];
        }
    }
#pragma unroll
    for (int i = 0; i < TM; i++) {
        const int row = m0 + ty * TM + i;
        float o[TN];
#pragma unroll
        for (int j = 0; j < TN; j++)
            o[j] = fmaxf(fmaf(acc[i][j], s[j], tt[j]), 0.0f);
        *(float4*)&C[(long)row * N + n0 + tx * TN]     = *(float4*)&o[0];
        *(float4*)&C[(long)row * N + n0 + tx * TN + 4] = *(float4*)&o[4];
    }
}

// ---------------------------------------------------------------------------
// Node head: out[row, c] = sigmoid(b[c] + sum_k H3[row,k] * W[k,c]) ; NC=8
// One thread per output element; weights (128x8) staged in smem.
// ---------------------------------------------------------------------------
__global__ __launch_bounds__(128)
void node_head_kernel(const float* __restrict__ H, const float* __restrict__ Wk,
                      const float* __restrict__ bias, float* __restrict__ out)
{
    __shared__ float ws[H3n * NCn];
    __shared__ float bs[NCn];
    for (int i = threadIdx.x; i < H3n * NCn; i += 128) ws[i] = Wk[i];
    if (threadIdx.x < NCn) bs[threadIdx.x] = bias[threadIdx.x];
    __syncthreads();

    const int idx = blockIdx.x * 128 + threadIdx.x;   // row*8 + col
    const int row = idx >> 3;
    const int col = idx & 7;
    const float* hr = H + (long)row * H3n;

    float a0 = 0.f, a1 = 0.f, a2 = 0.f, a3 = 0.f;
#pragma unroll
    for (int k = 0; k < H3n; k += 4) {
        a0 = fmaf(hr[k + 0], ws[(k + 0) * NCn + col], a0);
        a1 = fmaf(hr[k + 1], ws[(k + 1) * NCn + col], a1);
        a2 = fmaf(hr[k + 2], ws[(k + 2) * NCn + col], a2);
        a3 = fmaf(hr[k + 3], ws[(k + 3) * NCn + col], a3);
    }
    out[idx] = sigmoidf_(bs[col] + ((a0 + a1) + (a2 + a3)));
}

// ---------------------------------------------------------------------------
// Edge path, fully fused: gather node attrs -> 18->64 relu -> 64->64 relu
// -> 64->10 sigmoid. One thread per edge; all weights in smem (~24 KB).
// Weight LDS is warp-broadcast and rides the free issue slots between FFMAs
// (FFMA rt=2/SMSP), so the fused form runs at full FFMA rate.
// Layer-2 + head are chunked (16 h2 values at a time) to cap peak live
// registers at ~96 floats and guarantee no spills at 256 thr/CTA.
// Edges are batch-contiguous, so the 18 KB per-batch attr set stays L1-hot.
// ---------------------------------------------------------------------------
__global__ __launch_bounds__(256)
void edge_kernel(const float* __restrict__ bbox, const float* __restrict__ dirs,
                 const float* __restrict__ prio, const int* __restrict__ eidx,
                 const float* __restrict__ w1, const float* __restrict__ b1,
                 const float* __restrict__ w2, const float* __restrict__ b2,
                 const float* __restrict__ w3, const float* __restrict__ b3,
                 float* __restrict__ out)
{
    __shared__ float sw1[18 * 64];
    __shared__ float sw2[64 * 64];
    __shared__ float sw3[64 * 10];
    __shared__ float sb1[64], sb2[64], sb3[16];

    for (int i = threadIdx.x; i < 18 * 64; i += 256) sw1[i] = w1[i];
    for (int i = threadIdx.x; i < 64 * 64; i += 256) sw2[i] = w2[i];
    for (int i = threadIdx.x; i < 64 * 10; i += 256) sw3[i] = w3[i];
    if (threadIdx.x < 64) { sb1[threadIdx.x] = b1[threadIdx.x]; sb2[threadIdx.x] = b2[threadIdx.x]; }
    if (threadIdx.x < 10) sb3[threadIdx.x] = b3[threadIdx.x];
    __syncthreads();

    const int e    = blockIdx.x * 256 + threadIdx.x;
    const int bidx = e >> 15;            // / En (32768)
    const int w    = e & (En - 1);
    const int src  = eidx[bidx * 2 * En + w];
    const int dst  = eidx[bidx * 2 * En + En + w];

    float a[18];
    {
        const int sb = bidx * Nn + src;
        const float4 bv = *(const float4*)&bbox[sb * 4];
        a[0] = bv.x * INV_POS; a[1] = bv.y * INV_POS;
        a[2] = bv.z * INV_POS; a[3] = bv.w * INV_POS;
        const float4 dv = *(const float4*)&dirs[sb * 4];
        a[4] = dv.x; a[5] = dv.y; a[6] = dv.z; a[7] = dv.w;
        a[8] = prio[sb];

        const int db = bidx * Nn + dst;
        const float4 bv2 = *(const float4*)&bbox[db * 4];
        a[9]  = bv2.x * INV_POS; a[10] = bv2.y * INV_POS;
        a[11] = bv2.z * INV_POS; a[12] = bv2.w * INV_POS;
        const float4 dv2 = *(const float4*)&dirs[db * 4];
        a[13] = dv2.x; a[14] = dv2.y; a[15] = dv2.z; a[16] = dv2.w;
        a[17] = prio[db];
    }

    // layer 1: 18 -> 64 (h stays live through layer 2)
    float h[64];
#pragma unroll
    for (int j = 0; j < 64; j++) h[j] = sb1[j];
#pragma unroll
    for (int i = 0; i < 18; i++) {
        const float v = a[i];
#pragma unroll
        for (int j = 0; j < 64; j++) h[j] = fmaf(v, sw1[i * 64 + j], h[j]);
    }
#pragma unroll
    for (int j = 0; j < 64; j++) h[j] = fmaxf(h[j], 0.0f);

    // layer 2 + head, chunked: compute h2 16 columns at a time and fold each
    // chunk straight into the 10 head accumulators. Peak live ~= h(64)+16+o(10).
    float o[10];
#pragma unroll
    for (int c = 0; c < 10; c++) o[c] = sb3[c];

#pragma unroll
    for (int j0 = 0; j0 < 64; j0 += 16) {
        float h2[16];
#pragma unroll
        for (int j = 0; j < 16; j++) h2[j] = sb2[j0 + j];
#pragma unroll
        for (int i = 0; i < 64; i++) {
            const float v = h[i];
#pragma unroll
            for (int j = 0; j < 16; j++)
                h2[j] = fmaf(v, sw2[i * 64 + j0 + j], h2[j]);
        }
#pragma unroll
        for (int j = 0; j < 16; j++) {
            const float v = fmaxf(h2[j], 0.0f);
#pragma unroll
            for (int c = 0; c < 10; c++)
                o[c] = fmaf(v, sw3[(j0 + j) * 10 + c], o[c]);
        }
    }

    float* op = out + (long)e * 10;
#pragma unroll
    for (int c = 0; c < 10; c++) op[c] = sigmoidf_(o[c]);
}

// ---------------------------------------------------------------------------
extern "C" void kernel_launch(void* const* d_in, const int* in_sizes, int n_in,
                              void* d_out, int out_size)
{
    const float* roi  = (const float*)d_in[0];
    const float* bbox = (const float*)d_in[1];
    const float* dirs = (const float*)d_in[2];
    const float* prio = (const float*)d_in[3];
    const int*   eidx = (const int*)  d_in[4];
    const float* w1   = (const float*)d_in[5];
    const float* b1   = (const float*)d_in[6];
    const float* g1   = (const float*)d_in[7];
    const float* bb1  = (const float*)d_in[8];
    const float* rm1  = (const float*)d_in[9];
    const float* rv1  = (const float*)d_in[10];
    const float* w2   = (const float*)d_in[11];
    const float* b2   = (const float*)d_in[12];
    const float* g2   = (const float*)d_in[13];
    const float* bb2  = (const float*)d_in[14];
    const float* rm2  = (const float*)d_in[15];
    const float* rv2  = (const float*)d_in[16];
    const float* w3   = (const float*)d_in[17];
    const float* b3   = (const float*)d_in[18];
    const float* niw  = (const float*)d_in[19];
    const float* nib  = (const float*)d_in[20];
    const float* ew1  = (const float*)d_in[21];
    const float* eb1  = (const float*)d_in[22];
    const float* ew2  = (const float*)d_in[23];
    const float* eb2  = (const float*)d_in[24];
    const float* eiw  = (const float*)d_in[25];
    const float* eib  = (const float*)d_in[26];

    // stateless, deterministic address queries (no stream interaction; capture-safe)
    float *h1p, *h2p, *h3p;
    cudaGetSymbolAddress((void**)&h1p, g_h1);
    cudaGetSymbolAddress((void**)&h2p, g_h2);
    cudaGetSymbolAddress((void**)&h3p, g_h3);

    float* out_node = (float*)d_out;
    float* out_edge = (float*)d_out + (long)ROWS * NCn;

    // node MLP
    sgemm_fused<0><<<dim3(H1n / 128, ROWS / 128), 256>>>(
        roi, w1, b1, g1, bb1, rm1, rv1, h1p, ROWS, H1n, Fn);
    sgemm_fused<0><<<dim3(H2n / 128, ROWS / 128), 256>>>(
        h1p, w2, b2, g2, bb2, rm2, rv2, h2p, ROWS, H2n, H1n);
    sgemm_fused<1><<<dim3(H3n / 128, ROWS / 128), 256>>>(
        h2p, w3, b3, nullptr, nullptr, nullptr, nullptr, h3p, ROWS, H3n, H2n);
    node_head_kernel<<<ROWS * NCn / 128, 128>>>(h3p, niw, nib, out_node);

    // edge MLP (independent of node path)
    edge_kernel<<<TEn / 256, 256>>>(bbox, dirs, prio, eidx,
                                    ew1, eb1, ew2, eb2, eiw, eib, out_edge);
}

// round 9
// speedup vs baseline: 1.0704x; 1.0704x over previous
#include <cuda_runtime.h>

// ---------------------------------------------------------------------------
// GroundingNet fused forward — fp32 with packed fma.rn.f32x2 (FFMA2).
// R3 measured 1040us at the scalar-FFMA roofline (17.7 GFMA/ms); FFMA2 doubles
// fma-pipe throughput with bit-identical fp32 results.
// ---------------------------------------------------------------------------

namespace {
constexpr int Bn  = 32;
constexpr int Nn  = 512;
constexpr int Fn  = 1024;
constexpr int H1n = 512;
constexpr int H2n = 256;
constexpr int H3n = 128;
constexpr int NCn = 8;
constexpr int En  = 32768;                 // edges per batch
constexpr int ROWS = Bn * Nn;              // 16384
constexpr int TEn  = Bn * En;              // 1048576 total edges
constexpr float BN_EPS = 1e-5f;
constexpr float INV_POS = 1.0f / 1024.0f;
}

// scratch (static device allocation — no runtime allocs)
__device__ float g_h1[ROWS * H1n];
__device__ float g_h2[ROWS * H2n];
__device__ float g_h3[ROWS * H3n];

static __device__ __forceinline__ float sigmoidf_(float x) {
    return 1.0f / (1.0f + __expf(-x));
}

// ---- packed f32x2 helpers --------------------------------------------------
union F2 { unsigned long long u; float2 f; };

static __device__ __forceinline__ unsigned long long packdup(float x) {
    unsigned long long r;
    asm("mov.b64 %0, {%1, %1};" : "=l"(r) : "f"(x));
    return r;
}
// d = a * b + d (elementwise on the two packed fp32 lanes; IEEE fma per lane)
static __device__ __forceinline__ void fma2(unsigned long long& d,
                                            unsigned long long a,
                                            unsigned long long b) {
    asm("fma.rn.f32x2 %0, %1, %2, %0;" : "+l"(d) : "l"(a), "l"(b));
}

// ---------------------------------------------------------------------------
// Tiled SGEMM with fused epilogue, FFMA2 inner loop.
//   C[M,N] = epi(A[M,K] @ W[K,N])
//   EPI 0: BN + ReLU ; EPI 1: bias + ReLU
// BM=BN=128, BK=8, 256 threads, 8x8 per-thread tile (packed 8x4 f32x2),
// double-buffered smem. Requires M%128==0, N%128==0, K%8==0.
// ---------------------------------------------------------------------------
template<int EPI>
__global__ __launch_bounds__(256, 2)
void sgemm_fused(const float* __restrict__ A, const float* __restrict__ W,
                 const float* __restrict__ bias,
                 const float* __restrict__ bng, const float* __restrict__ bnb,
                 const float* __restrict__ bnrm, const float* __restrict__ bnrv,
                 float* __restrict__ C, int M, int N, int K)
{
    constexpr int BM = 128, BN = 128, BK = 8, TM = 8, TN = 8;
    __shared__ __align__(16) float As[2][BK][BM];
    __shared__ __align__(16) float Bs[2][BK][BN];

    const int m0  = blockIdx.y * BM;
    const int n0  = blockIdx.x * BN;
    const int tid = threadIdx.x;
    const int tx  = tid & 15;   // N direction (16 * TN = 128)
    const int ty  = tid >> 4;   // M direction (16 * TM = 128)

    // global->smem load mapping (one float4 per thread per tile)
    const int arow = tid >> 1;            // 0..127
    const int acol = (tid & 1) * 4;       // 0 or 4
    const int wrow = tid >> 5;            // 0..7
    const int wcol = (tid & 31) * 4;      // 0..124

    const float* Aptr = A + (long)(m0 + arow) * K + acol;
    const float* Wptr = W + (long)wrow * N + n0 + wcol;

    unsigned long long acc[TM][TN / 2];
#pragma unroll
    for (int i = 0; i < TM; i++)
#pragma unroll
        for (int j = 0; j < TN / 2; j++) acc[i][j] = 0ull;

    // preload stage 0
    {
        float4 av = *(const float4*)Aptr;
        As[0][acol + 0][arow] = av.x;
        As[0][acol + 1][arow] = av.y;
        As[0][acol + 2][arow] = av.z;
        As[0][acol + 3][arow] = av.w;
        *(float4*)&Bs[0][wrow][wcol] = *(const float4*)Wptr;
    }
    __syncthreads();

    const int T = K / BK;
    for (int t = 0; t < T; t++) {
        float4 av, wv;
        if (t + 1 < T) {
            av = *(const float4*)(Aptr + (t + 1) * BK);
            wv = *(const float4*)(Wptr + (long)(t + 1) * BK * N);
        }
        const int cur = t & 1;
#pragma unroll
        for (int kk = 0; kk < BK; kk++) {
            float a[TM];
            *(float4*)&a[0] = *(const float4*)&As[cur][kk][ty * TM];
            *(float4*)&a[4] = *(const float4*)&As[cur][kk][ty * TM + 4];
            unsigned long long bp[TN / 2];
#pragma unroll
            for (int j = 0; j < TN / 2; j++)
                bp[j] = *(const unsigned long long*)&Bs[cur][kk][tx * TN + 2 * j];
            unsigned long long ad[TM];
#pragma unroll
            for (int i = 0; i < TM; i++) ad[i] = packdup(a[i]);
#pragma unroll
            for (int i = 0; i < TM; i++)
#pragma unroll
                for (int j = 0; j < TN / 2; j++)
                    fma2(acc[i][j], ad[i], bp[j]);
        }
        if (t + 1 < T) {
            const int nxt = cur ^ 1;
            As[nxt][acol + 0][arow] = av.x;
            As[nxt][acol + 1][arow] = av.y;
            As[nxt][acol + 2][arow] = av.z;
            As[nxt][acol + 3][arow] = av.w;
            *(float4*)&Bs[nxt][wrow][wcol] = wv;
            __syncthreads();
        }
    }

    // fused epilogue (scalar; negligible vs mainloop)
    float s[TN], tt[TN];
#pragma unroll
    for (int j = 0; j < TN; j++) {
        const int col = n0 + tx * TN + j;
        if (EPI == 0) {
            const float sc = bng[col] * rsqrtf(bnrv[col] + BN_EPS);
            s[j]  = sc;
            tt[j] = bnb[col] + sc * (bias[col] - bnrm[col]);
        } else {
            s[j]  = 1.0f;
            tt[j] = bias[col];
        }
    }
#pragma unroll
    for (int i = 0; i < TM; i++) {
        const int row = m0 + ty * TM + i;
        float o[TN];
#pragma unroll
        for (int j = 0; j < TN / 2; j++) {
            F2 t; t.u = acc[i][j];
            o[2 * j]     = fmaxf(fmaf(t.f.x, s[2 * j],     tt[2 * j]),     0.0f);
            o[2 * j + 1] = fmaxf(fmaf(t.f.y, s[2 * j + 1], tt[2 * j + 1]), 0.0f);
        }
        *(float4*)&C[(long)row * N + n0 + tx * TN]     = *(float4*)&o[0];
        *(float4*)&C[(long)row * N + n0 + tx * TN + 4] = *(float4*)&o[4];
    }
}

// ---------------------------------------------------------------------------
// Node head: out[row, c] = sigmoid(b[c] + sum_k H3[row,k] * W[k,c]) ; NC=8
// ---------------------------------------------------------------------------
__global__ __launch_bounds__(128)
void node_head_kernel(const float* __restrict__ H, const float* __restrict__ Wk,
                      const float* __restrict__ bias, float* __restrict__ out)
{
    __shared__ float ws[H3n * NCn];
    __shared__ float bs[NCn];
    for (int i = threadIdx.x; i < H3n * NCn; i += 128) ws[i] = Wk[i];
    if (threadIdx.x < NCn) bs[threadIdx.x] = bias[threadIdx.x];
    __syncthreads();

    const int idx = blockIdx.x * 128 + threadIdx.x;   // row*8 + col
    const int row = idx >> 3;
    const int col = idx & 7;
    const float* hr = H + (long)row * H3n;

    float a0 = 0.f, a1 = 0.f, a2 = 0.f, a3 = 0.f;
#pragma unroll
    for (int k = 0; k < H3n; k += 4) {
        a0 = fmaf(hr[k + 0], ws[(k + 0) * NCn + col], a0);
        a1 = fmaf(hr[k + 1], ws[(k + 1) * NCn + col], a1);
        a2 = fmaf(hr[k + 2], ws[(k + 2) * NCn + col], a2);
        a3 = fmaf(hr[k + 3], ws[(k + 3) * NCn + col], a3);
    }
    out[idx] = sigmoidf_(bs[col] + ((a0 + a1) + (a2 + a3)));
}

// ---------------------------------------------------------------------------
// Edge path, fully fused + FFMA2: gather -> 18->64 relu -> 64->64 relu
// -> 64->10 sigmoid. One thread per edge; all weights in smem.
// Accumulation order per output element identical to the scalar version.
// ---------------------------------------------------------------------------
__global__ __launch_bounds__(256)
void edge_kernel(const float* __restrict__ bbox, const float* __restrict__ dirs,
                 const float* __restrict__ prio, const int* __restrict__ eidx,
                 const float* __restrict__ w1, const float* __restrict__ b1,
                 const float* __restrict__ w2, const float* __restrict__ b2,
                 const float* __restrict__ w3, const float* __restrict__ b3,
                 float* __restrict__ out)
{
    __shared__ __align__(16) float sw1[18 * 64];
    __shared__ __align__(16) float sw2[64 * 64];
    __shared__ __align__(16) float sw3[64 * 10];
    __shared__ __align__(16) float sb1[64];
    __shared__ __align__(16) float sb2[64];
    __shared__ __align__(16) float sb3[16];

    for (int i = threadIdx.x; i < 18 * 64; i += 256) sw1[i] = w1[i];
    for (int i = threadIdx.x; i < 64 * 64; i += 256) sw2[i] = w2[i];
    for (int i = threadIdx.x; i < 64 * 10; i += 256) sw3[i] = w3[i];
    if (threadIdx.x < 64) { sb1[threadIdx.x] = b1[threadIdx.x]; sb2[threadIdx.x] = b2[threadIdx.x]; }
    if (threadIdx.x < 10) sb3[threadIdx.x] = b3[threadIdx.x];
    __syncthreads();

    const int e    = blockIdx.x * 256 + threadIdx.x;
    const int bidx = e >> 15;            // / En (32768)
    const int w    = e & (En - 1);
    const int src  = eidx[bidx * 2 * En + w];
    const int dst  = eidx[bidx * 2 * En + En + w];

    float a[18];
    {
        const int sb = bidx * Nn + src;
        const float4 bv = *(const float4*)&bbox[sb * 4];
        a[0] = bv.x * INV_POS; a[1] = bv.y * INV_POS;
        a[2] = bv.z * INV_POS; a[3] = bv.w * INV_POS;
        const float4 dv = *(const float4*)&dirs[sb * 4];
        a[4] = dv.x; a[5] = dv.y; a[6] = dv.z; a[7] = dv.w;
        a[8] = prio[sb];

        const int db = bidx * Nn + dst;
        const float4 bv2 = *(const float4*)&bbox[db * 4];
        a[9]  = bv2.x * INV_POS; a[10] = bv2.y * INV_POS;
        a[11] = bv2.z * INV_POS; a[12] = bv2.w * INV_POS;
        const float4 dv2 = *(const float4*)&dirs[db * 4];
        a[13] = dv2.x; a[14] = dv2.y; a[15] = dv2.z; a[16] = dv2.w;
        a[17] = prio[db];
    }

    // layer 1: 18 -> 64, packed pairs along output dim
    unsigned long long h[32];
#pragma unroll
    for (int jp = 0; jp < 32; jp++)
        h[jp] = *(const unsigned long long*)&sb1[2 * jp];
#pragma unroll
    for (int i = 0; i < 18; i++) {
        const unsigned long long v = packdup(a[i]);
        const unsigned long long* wr = (const unsigned long long*)&sw1[i * 64];
#pragma unroll
        for (int jp = 0; jp < 32; jp++) fma2(h[jp], v, wr[jp]);
    }
    // relu in place
#pragma unroll
    for (int jp = 0; jp < 32; jp++) {
        F2 t; t.u = h[jp];
        t.f.x = fmaxf(t.f.x, 0.0f);
        t.f.y = fmaxf(t.f.y, 0.0f);
        h[jp] = t.u;
    }

    // layer 2 + head, chunked 16 outputs (8 pairs) at a time
    unsigned long long o[5];
#pragma unroll
    for (int c = 0; c < 5; c++)
        o[c] = *(const unsigned long long*)&sb3[2 * c];

#pragma unroll
    for (int j0 = 0; j0 < 64; j0 += 16) {
        unsigned long long h2[8];
#pragma unroll
        for (int jp = 0; jp < 8; jp++)
            h2[jp] = *(const unsigned long long*)&sb2[j0 + 2 * jp];
#pragma unroll
        for (int ip = 0; ip < 32; ip++) {
            F2 t; t.u = h[ip];
            const unsigned long long vx = packdup(t.f.x);
            const unsigned long long vy = packdup(t.f.y);
            const unsigned long long* w2rx =
                (const unsigned long long*)&sw2[(2 * ip) * 64 + j0];
            const unsigned long long* w2ry =
                (const unsigned long long*)&sw2[(2 * ip + 1) * 64 + j0];
#pragma unroll
            for (int jp = 0; jp < 8; jp++) fma2(h2[jp], vx, w2rx[jp]);
#pragma unroll
            for (int jp = 0; jp < 8; jp++) fma2(h2[jp], vy, w2ry[jp]);
        }
        // relu + fold into head accumulators (j ascending => same order)
#pragma unroll
        for (int jp = 0; jp < 8; jp++) {
            F2 t; t.u = h2[jp];
            const unsigned long long v0 = packdup(fmaxf(t.f.x, 0.0f));
            const unsigned long long v1 = packdup(fmaxf(t.f.y, 0.0f));
            const unsigned long long* w3r0 =
                (const unsigned long long*)&sw3[(j0 + 2 * jp) * 10];
            const unsigned long long* w3r1 =
                (const unsigned long long*)&sw3[(j0 + 2 * jp + 1) * 10];
#pragma unroll
            for (int c = 0; c < 5; c++) fma2(o[c], v0, w3r0[c]);
#pragma unroll
            for (int c = 0; c < 5; c++) fma2(o[c], v1, w3r1[c]);
        }
    }

    float* op = out + (long)e * 10;
#pragma unroll
    for (int c = 0; c < 5; c++) {
        F2 t; t.u = o[c];
        op[2 * c]     = sigmoidf_(t.f.x);
        op[2 * c + 1] = sigmoidf_(t.f.y);
    }
}

// ---------------------------------------------------------------------------
extern "C" void kernel_launch(void* const* d_in, const int* in_sizes, int n_in,
                              void* d_out, int out_size)
{
    const float* roi  = (const float*)d_in[0];
    const float* bbox = (const float*)d_in[1];
    const float* dirs = (const float*)d_in[2];
    const float* prio = (const float*)d_in[3];
    const int*   eidx = (const int*)  d_in[4];
    const float* w1   = (const float*)d_in[5];
    const float* b1   = (const float*)d_in[6];
    const float* g1   = (const float*)d_in[7];
    const float* bb1  = (const float*)d_in[8];
    const float* rm1  = (const float*)d_in[9];
    const float* rv1  = (const float*)d_in[10];
    const float* w2   = (const float*)d_in[11];
    const float* b2   = (const float*)d_in[12];
    const float* g2   = (const float*)d_in[13];
    const float* bb2  = (const float*)d_in[14];
    const float* rm2  = (const float*)d_in[15];
    const float* rv2  = (const float*)d_in[16];
    const float* w3   = (const float*)d_in[17];
    const float* b3   = (const float*)d_in[18];
    const float* niw  = (const float*)d_in[19];
    const float* nib  = (const float*)d_in[20];
    const float* ew1  = (const float*)d_in[21];
    const float* eb1  = (const float*)d_in[22];
    const float* ew2  = (const float*)d_in[23];
    const float* eb2  = (const float*)d_in[24];
    const float* eiw  = (const float*)d_in[25];
    const float* eib  = (const float*)d_in[26];

    // stateless, deterministic address queries (capture-safe)
    float *h1p, *h2p, *h3p;
    cudaGetSymbolAddress((void**)&h1p, g_h1);
    cudaGetSymbolAddress((void**)&h2p, g_h2);
    cudaGetSymbolAddress((void**)&h3p, g_h3);

    float* out_node = (float*)d_out;
    float* out_edge = (float*)d_out + (long)ROWS * NCn;

    // node MLP
    sgemm_fused<0><<<dim3(H1n / 128, ROWS / 128), 256>>>(
        roi, w1, b1, g1, bb1, rm1, rv1, h1p, ROWS, H1n, Fn);
    sgemm_fused<0><<<dim3(H2n / 128, ROWS / 128), 256>>>(
        h1p, w2, b2, g2, bb2, rm2, rv2, h2p, ROWS, H2n, H1n);
    sgemm_fused<1><<<dim3(H3n / 128, ROWS / 128), 256>>>(
        h2p, w3, b3, nullptr, nullptr, nullptr, nullptr, h3p, ROWS, H3n, H2n);
    node_head_kernel<<<ROWS * NCn / 128, 128>>>(h3p, niw, nib, out_node);

    // edge MLP (independent of node path)
    edge_kernel<<<TEn / 256, 256>>>(bbox, dirs, prio, eidx,
                                    ew1, eb1, ew2, eb2, eiw, eib, out_edge);
}